// round 13
// baseline (speedup 1.0000x reference)
#include <cuda_runtime.h>
#include <cuda.h>
#include <cstdint>
#include <cstdio>
#include <math.h>

// ============================================================================
// BlockCirculant via DFT factorization (63x fewer FLOPs than dense GEMM):
//   out[b, i*128+t] = ifft_t( sum_j fft(x_d block j) * conj(fft(W[i,j])) ) + bias
// All GEMMs legacy mma.sync m16n8k8 tf32 (A rna-rounded in-register, B
// rna-prebuilt). 4-kernel pipeline -- transposes FUSED into GEMM epilogues
// as scattered float2 stores (the re/im column pairs are adjacent in the
// transposed layouts, so each accumulator pair stores directly):
//   P : one merged prep kernel (F_j, Op[fs], B3) via inline sincospif
//   G1: Xg[fs][b][2j+c]  = (x[b][j*128+s] @ F_j[n][s]^T) scattered   (K=128)
//   G2: Z[b*32+i][2fs+c] = (Xg[fs][b][.] @ Op[fs]^T)     scattered   (K=64)
//   G3: out[r][t]        = Z[r][.] @ B3[t][.]^T + bias   linear      (K=128)
// Xg lives in bufA, Z in bufB.
// Freq packing: n = 2*fs + c; slot fs=0 carries (f=0, f=64[Nyquist]) real bins.
// ============================================================================

static constexpr int DIMN = 4096;

__device__ float g_bufA[(size_t)DIMN * DIMN];   // Xg [64 fs][4096 b][64]
__device__ float g_bufB[(size_t)DIMN * DIMN];   // Z  [131072 r][128]
__device__ float g_Fj[32 * 128 * 128];
__device__ float g_Op[64 * 64 * 64];
__device__ float g_B3[128 * 128];

// ------------------------------------------------------------ PTX helpers
__device__ __forceinline__ uint32_t smem_u32(const void* p) {
    uint32_t a;
    asm("{ .reg .u64 t; cvta.to.shared.u64 t, %1; cvt.u32.u64 %0, t; }"
        : "=r"(a) : "l"(p));
    return a;
}
__device__ __forceinline__ uint32_t elect_one() {
    uint32_t pred;
    asm volatile(
        "{\n\t.reg .pred p;\n\telect.sync _|p, 0xFFFFFFFF;\n\t"
        "selp.b32 %0, 1, 0, p;\n\t}" : "=r"(pred));
    return pred;
}
#define MBARRIER_INIT(addr, cnt) \
    asm volatile("mbarrier.init.shared.b64 [%0], %1;" \
                 :: "r"((uint32_t)(addr)), "r"((uint32_t)(cnt)) : "memory")
#define MBARRIER_ARRIVE(addr) \
    asm volatile("mbarrier.arrive.shared.b64 _, [%0];" \
                 :: "r"((uint32_t)(addr)) : "memory")
#define MBARRIER_EXPECT_TX(addr, bytes) \
    asm volatile("mbarrier.arrive.expect_tx.shared.b64 _, [%0], %1;" \
                 :: "r"((uint32_t)(addr)), "r"((uint32_t)(bytes)) : "memory")
#define MBARRIER_WAIT_PARITY(addr, parity) do {                                  \
    uint32_t _mbar = (uint32_t)(addr);                                           \
    uint32_t _par  = (uint32_t)(parity);                                         \
    uint32_t _done;                                                              \
    asm volatile(                                                                \
        "{\n\t.reg .pred p;\n\t"                                                 \
        "mbarrier.try_wait.parity.acquire.cta.shared::cta.b64 p, [%1], %2;\n\t"  \
        "selp.b32 %0, 1, 0, p;\n\t}"                                             \
        : "=r"(_done) : "r"(_mbar), "r"(_par) : "memory");                       \
    if (!_done) {                                                                \
        asm volatile(                                                            \
            "{\n\t.reg .pred P1;\n\t"                                            \
            "WAIT_LOOP_%=:\n\t"                                                  \
            "mbarrier.try_wait.parity.acquire.cta.shared::cta.b64 P1, [%0], %1, 0x989680;\n\t" \
            "@P1 bra.uni WAIT_DONE_%=;\n\t"                                      \
            "bra.uni WAIT_LOOP_%=;\n\t"                                          \
            "WAIT_DONE_%=:\n\t}"                                                 \
            :: "r"(_mbar), "r"(_par) : "memory");                                \
    }                                                                            \
} while (0)
#define TMA_LOAD_2D(smem_addr, tmap, cx, cy, mbar)                               \
    asm volatile(                                                                \
        "cp.async.bulk.tensor.2d.shared::cta.global.tile.mbarrier::complete_tx::bytes " \
        "[%0], [%1, {%2, %3}], [%4];"                                            \
        :: "r"((uint32_t)(smem_addr)), "l"(tmap),                                \
           "r"((int32_t)(cx)), "r"((int32_t)(cy)),                               \
           "r"((uint32_t)(mbar)) : "memory")
#define LDSM_X4(d0, d1, d2, d3, addr)                                            \
    asm volatile("ldmatrix.sync.aligned.m8n8.x4.shared.b16 {%0,%1,%2,%3}, [%4];" \
                 : "=r"(d0), "=r"(d1), "=r"(d2), "=r"(d3) : "r"(addr))

__device__ __forceinline__ void mma_tf32(float* c, const uint32_t* a,
                                         const uint32_t* b) {
    asm volatile(
        "mma.sync.aligned.m16n8k8.row.col.f32.tf32.tf32.f32 "
        "{%0,%1,%2,%3}, {%4,%5,%6,%7}, {%8,%9}, {%0,%1,%2,%3};"
        : "+f"(c[0]), "+f"(c[1]), "+f"(c[2]), "+f"(c[3])
        : "r"(a[0]), "r"(a[1]), "r"(a[2]), "r"(a[3]), "r"(b[0]), "r"(b[1]));
}
__device__ __forceinline__ float tf32r(float v) {
    uint32_t u;
    asm("cvt.rna.tf32.f32 %0, %1;" : "=r"(u) : "f"(v));
    return __uint_as_float(u);
}
// cos/sin of 2*pi*m/128 = pi*(m/64), m in [0,128)
__device__ __forceinline__ float2 twiddle(int m) {
    float s, c;
    sincospif((float)m * (1.0f / 64.0f), &s, &c);
    return make_float2(c, s);
}

// ------------------------------------------------------------ merged prep
// blocks [0,2048): F_j ; [2048,2304): Op ; [2304,2368): B3
__global__ void __launch_bounds__(256)
bc_prep(const float* __restrict__ W, const float* __restrict__ Dvec) {
    const int bx = blockIdx.x;
    if (bx < 2048) {
        // F_j[j][n][s] = F1[n][s] * D[j*128+s], tf32-rounded
        int idx = bx * 256 + threadIdx.x;          // 0..524287
        int j = idx >> 14;
        int n = (idx >> 7) & 127;
        int s = idx & 127;
        float base;
        if (n == 0)      base = 1.0f;
        else if (n == 1) base = (s & 1) ? -1.0f : 1.0f;       // f=64 (Nyquist)
        else {
            float2 w = twiddle(((n >> 1) * s) & 127);
            base = (n & 1) ? w.y : w.x;                       // sin : cos
        }
        g_Fj[idx] = tf32r(base * Dvec[j * 128 + s]);
    } else if (bx < 2304) {
        // Op[fs][2i+c][2j+c'] from aW/bW of W[i][j][.]
        int tid = (bx - 2048) * 256 + threadIdx.x; // 0..65535
        int fs = tid >> 10;
        int i  = (tid >> 5) & 31;
        int j  = tid & 31;
        const float* w = W + (i * 32 + j) * 128;
        float* op = g_Op + (size_t)fs * 4096;
        if (fs == 0) {
            float a0 = 0.f, a64 = 0.f;
            for (int u = 0; u < 128; u++) {
                float wu = w[u];
                a0  += wu;
                a64 += (u & 1) ? -wu : wu;
            }
            op[(2 * i) * 64 + 2 * j]         = tf32r(a0);
            op[(2 * i) * 64 + 2 * j + 1]     = 0.f;
            op[(2 * i + 1) * 64 + 2 * j]     = 0.f;
            op[(2 * i + 1) * 64 + 2 * j + 1] = tf32r(a64);
        } else {
            float aw = 0.f, bw = 0.f;
            for (int u = 0; u < 128; u++) {
                float2 t = twiddle((fs * u) & 127);
                float wu = w[u];
                aw += wu * t.x;
                bw += wu * t.y;
            }
            // Y_re = aX*aW + bX*bW ; Y_im = aX*bW - bX*aW
            op[(2 * i) * 64 + 2 * j]         = tf32r(aw);
            op[(2 * i) * 64 + 2 * j + 1]     = tf32r(bw);
            op[(2 * i + 1) * 64 + 2 * j]     = tf32r(bw);
            op[(2 * i + 1) * 64 + 2 * j + 1] = tf32r(-aw);
        }
    } else {
        // B3[t][n'] inverse transform
        int idx = (bx - 2304) * 256 + threadIdx.x; // 0..16383
        int t = idx >> 7;
        int n = idx & 127;
        float v;
        if (n == 0)      v = 1.0f / 128.0f;
        else if (n == 1) v = ((t & 1) ? -1.0f : 1.0f) / 128.0f;
        else {
            float2 w = twiddle(((n >> 1) * t) & 127);
            v = ((n & 1) ? -w.y : w.x) * (2.0f / 128.0f);     // cos(+), sin(-)
        }
        g_B3[idx] = tf32r(v);
    }
}

// ------------------------------------------------------------ main GEMM
// C[128 x 128] = A[128 x 128] @ B^T, K=128 (4 chunks of 32), 2-stage TMA
// pipeline with backpressure, 2 CTAs/SM. 288 thr: 8 compute warps (64x32)
// + producer warp.
// G1 (bias==nullptr): grid(32,32) A=x, B=Fj; epilogue scatters into
//   Xg[fs][b][2*jb+c] (float2 @ fs*131072 + b*32 + jb).
// G3 (bias!=nullptr): grid(1024,1) A=Z, B=B3; linear store + bias.
static constexpr int G_ABYTES = 128 * 32 * 4;            // 16 KB
static constexpr int G_STAGE  = 2 * G_ABYTES;            // A + B = 32 KB
static constexpr int SMEM_G   = 2048 + 2 * G_STAGE;      // 66 KB -> 2 CTAs/SM

__global__ void __launch_bounds__(288, 2)
bc_gemm_tf32(const __grid_constant__ CUtensorMap tma_a,
             const __grid_constant__ CUtensorMap tma_b,
             float* __restrict__ outp,
             const float* __restrict__ bias) {
    extern __shared__ char smem[];
    const uint32_t raw       = smem_u32(smem);
    const uint32_t bar_full  = (raw + 15u) & ~7u;        // 2 barriers
    const uint32_t bar_empty = bar_full + 16;            // 2 barriers
    const uint32_t tiles     = (raw + 1024u + 1023u) & ~1023u;

    const int tid  = threadIdx.x;
    const int wid  = tid >> 5;
    const int lane = tid & 31;
    const int mt   = blockIdx.x;
    const int jb   = blockIdx.y;

    if (tid == 0) {
        for (int s = 0; s < 2; s++) {
            MBARRIER_INIT(bar_full + 8 * s, 1);   // tx-based
            MBARRIER_INIT(bar_empty + 8 * s, 8);  // 8 compute warps
        }
        asm volatile("fence.proxy.async.shared::cta;" ::: "memory");
    }
    __syncthreads();

    if (wid == 8) {
        if (elect_one()) {
            int stage = 0, phase = 1;   // parity 1: first 2 empty-waits pass
            for (int kt = 0; kt < 4; kt++) {
                MBARRIER_WAIT_PARITY(bar_empty + 8 * stage, phase);
                MBARRIER_EXPECT_TX(bar_full + 8 * stage, G_STAGE);
                uint32_t dst = tiles + stage * G_STAGE;
                TMA_LOAD_2D(dst,            &tma_a, jb * 128 + kt * 32, mt * 128, bar_full + 8 * stage);
                TMA_LOAD_2D(dst + G_ABYTES, &tma_b, kt * 32,            jb * 128, bar_full + 8 * stage);
                if (++stage == 2) { stage = 0; phase ^= 1; }
            }
        }
        return;
    }

    const int mo = (wid & 1) * 64;   // 2 warp rows (M=128)
    const int no = (wid >> 1) * 32;  // 4 warp cols (N=128)

    // ldmatrix offsets (SW128: 16B chunk ^= row&7; mo/no mult of 8 -> row&7==rr)
    uint32_t offA[4], offB[4];
    {
        const int t = lane >> 3, rr = lane & 7;
#pragma unroll
        for (int ks = 0; ks < 4; ks++) {
            int rowA = mo + (t & 1) * 8 + rr;
            int chA  = ks * 2 + (t >> 1);
            offA[ks] = rowA * 128 + ((chA ^ rr) << 4);
            int rowB = no + (t >> 1) * 8 + rr;
            int chB  = ks * 2 + (t & 1);
            offB[ks] = rowB * 128 + ((chB ^ rr) << 4);
        }
    }

    float c[4][4][4];
#pragma unroll
    for (int i = 0; i < 4; i++)
#pragma unroll
        for (int j = 0; j < 4; j++)
#pragma unroll
            for (int q = 0; q < 4; q++) c[i][j][q] = 0.0f;

    int stage = 0, phase = 0;
#pragma unroll 1
    for (int kt = 0; kt < 4; kt++) {
        MBARRIER_WAIT_PARITY(bar_full + 8 * stage, phase);
        const uint32_t sa = tiles + stage * G_STAGE;
        const uint32_t sb = sa + G_ABYTES;
#pragma unroll
        for (int ks = 0; ks < 4; ks++) {
            uint32_t a[4][4], b[4][2];
#pragma unroll
            for (int i = 0; i < 4; i++)
                LDSM_X4(a[i][0], a[i][1], a[i][2], a[i][3],
                        sa + offA[ks] + i * 2048);
            LDSM_X4(b[0][0], b[0][1], b[1][0], b[1][1], sb + offB[ks]);
            LDSM_X4(b[2][0], b[2][1], b[3][0], b[3][1], sb + offB[ks] + 2048);
            // rna-round A in-register
#pragma unroll
            for (int i = 0; i < 4; i++)
#pragma unroll
                for (int q = 0; q < 4; q++) {
                    float v = __uint_as_float(a[i][q]);
                    asm("cvt.rna.tf32.f32 %0, %1;" : "=r"(a[i][q]) : "f"(v));
                }
#pragma unroll
            for (int i = 0; i < 4; i++)
#pragma unroll
                for (int j = 0; j < 4; j++)
                    mma_tf32(c[i][j], a[i], b[j]);
        }
        if (elect_one()) MBARRIER_ARRIVE(bar_empty + 8 * stage);
        if (++stage == 2) { stage = 0; phase ^= 1; }
    }

    const int g   = lane >> 2;
    const int tig = lane & 3;
    if (bias == nullptr) {
        // ---- G1 epilogue: scatter into Xg[fs][b][2*jb + c] ----
        // float2 index = fs*131072 + b*32 + jb  (Xg as [64][4096][32] float2)
        float2* xg = reinterpret_cast<float2*>(outp);
#pragma unroll
        for (int i = 0; i < 4; i++) {
            const int b0 = mt * 128 + mo + i * 16 + g;     // global batch row
#pragma unroll
            for (int j = 0; j < 4; j++) {
                const int col = no + j * 8 + tig * 2;      // n (even)
                const int fs  = col >> 1;
                xg[(size_t)fs * 131072 + (size_t)b0 * 32 + jb] =
                    make_float2(c[i][j][0], c[i][j][1]);
                xg[(size_t)fs * 131072 + (size_t)(b0 + 8) * 32 + jb] =
                    make_float2(c[i][j][2], c[i][j][3]);
            }
        }
    } else {
        // ---- G3 epilogue: linear (ldc=128) + bias[(r&31)*128 + col] ----
        const size_t rowbase = (size_t)mt * 128;           // grid.y == 1
#pragma unroll
        for (int i = 0; i < 4; i++) {
            const int r0l = mo + i * 16 + g;
            float* o0 = outp + (rowbase + r0l) * 128;
            float* o1 = o0 + 8 * 128;
#pragma unroll
            for (int j = 0; j < 4; j++) {
                const int col = no + j * 8 + tig * 2;
                const float* b0 = bias + ((r0l) & 31) * 128 + col;
                const float* b1 = bias + ((r0l + 8) & 31) * 128 + col;
                float2 v0 = {c[i][j][0] + b0[0], c[i][j][1] + b0[1]};
                float2 v1 = {c[i][j][2] + b1[0], c[i][j][3] + b1[1]};
                *reinterpret_cast<float2*>(o0 + col) = v0;
                *reinterpret_cast<float2*>(o1 + col) = v1;
            }
        }
    }
}

// ------------------------------------------------------------ G2 kernel
// Per fs: C[256 x 64] = Xg[256 x 64] @ Op[fs]^T, K=64 (two 32-col halves).
// 256 thr = 8 compute warps (warp tile 32x64); thread 0 issues TMA.
// Epilogue scatters into Z[(b*32+i)][2fs+c] (float2 @ (b*32+i)*64 + fs).
static constexpr int G2_SMEM = 2048 + 81920;

__global__ void __launch_bounds__(256, 2)
bc_g2(const __grid_constant__ CUtensorMap tma_xg,
      const __grid_constant__ CUtensorMap tma_op,
      float* __restrict__ outp) {
    extern __shared__ char smem[];
    const uint32_t raw   = smem_u32(smem);
    const uint32_t bar   = (raw + 15u) & ~7u;
    const uint32_t tiles = (raw + 1024u + 1023u) & ~1023u;

    const int tid  = threadIdx.x;
    const int w    = tid >> 5;
    const int lane = tid & 31;
    const int mt   = blockIdx.x;     // 16 b-tiles of 256
    const int fs   = blockIdx.y;     // 64 freq slots

    if (tid == 0) {
        MBARRIER_INIT(bar, 1);
        asm volatile("fence.proxy.async.shared::cta;" ::: "memory");
    }
    __syncthreads();
    if (tid == 0) {
        MBARRIER_EXPECT_TX(bar, 81920);
        int ya = fs * 4096 + mt * 256;
        TMA_LOAD_2D(tiles,         &tma_xg, 0,  ya,      bar);
        TMA_LOAD_2D(tiles + 32768, &tma_xg, 32, ya,      bar);
        TMA_LOAD_2D(tiles + 65536, &tma_op, 0,  fs * 64, bar);
        TMA_LOAD_2D(tiles + 73728, &tma_op, 32, fs * 64, bar);
    }

    uint32_t offA[4], offB[4];
    {
        const int t = lane >> 3, rr = lane & 7;
#pragma unroll
        for (int kk = 0; kk < 4; kk++) {
            int rowA = w * 32 + (t & 1) * 8 + rr;
            int chA  = kk * 2 + (t >> 1);
            offA[kk] = rowA * 128 + ((chA ^ rr) << 4);
            int rowB = (t >> 1) * 8 + rr;
            int chB  = kk * 2 + (t & 1);
            offB[kk] = rowB * 128 + ((chB ^ rr) << 4);
        }
    }

    float c[2][8][4];
#pragma unroll
    for (int i = 0; i < 2; i++)
#pragma unroll
        for (int j = 0; j < 8; j++)
#pragma unroll
            for (int q = 0; q < 4; q++) c[i][j][q] = 0.0f;

    MBARRIER_WAIT_PARITY(bar, 0);

#pragma unroll
    for (int h = 0; h < 2; h++) {
        const uint32_t sa = tiles + h * 32768;
        const uint32_t sb = tiles + 65536 + h * 8192;
#pragma unroll
        for (int kk = 0; kk < 4; kk++) {
            uint32_t a[2][4], b[8][2];
#pragma unroll
            for (int i = 0; i < 2; i++)
                LDSM_X4(a[i][0], a[i][1], a[i][2], a[i][3],
                        sa + offA[kk] + i * 2048);
#pragma unroll
            for (int np = 0; np < 4; np++)
                LDSM_X4(b[2 * np][0], b[2 * np][1], b[2 * np + 1][0], b[2 * np + 1][1],
                        sb + offB[kk] + np * 2048);
#pragma unroll
            for (int i = 0; i < 2; i++)
#pragma unroll
                for (int q = 0; q < 4; q++) {
                    float v = __uint_as_float(a[i][q]);
                    asm("cvt.rna.tf32.f32 %0, %1;" : "=r"(a[i][q]) : "f"(v));
                }
#pragma unroll
            for (int i = 0; i < 2; i++)
#pragma unroll
                for (int j = 0; j < 8; j++)
                    mma_tf32(c[i][j], a[i], b[j]);
        }
    }

    // ---- epilogue: scatter into Z[(b*32+i)][2fs+c] ----
    // float2 index = (b*32 + i)*64 + fs   (Z as [131072][64] float2)
    float2* z = reinterpret_cast<float2*>(outp);
    const int b_base = mt * 256 + w * 32;
    const int g   = lane >> 2;
    const int tig = lane & 3;
#pragma unroll
    for (int ii = 0; ii < 2; ii++) {
        const int b0 = b_base + ii * 16 + g;
        const int b1 = b0 + 8;
#pragma unroll
        for (int j = 0; j < 8; j++) {
            const int i = j * 4 + tig;                 // = (j*8 + tig*2) >> 1
            z[((size_t)b0 * 32 + i) * 64 + fs] = make_float2(c[ii][j][0], c[ii][j][1]);
            z[((size_t)b1 * 32 + i) * 64 + fs] = make_float2(c[ii][j][2], c[ii][j][3]);
        }
    }
}

// ------------------------------------------------------------ host launch
extern "C" void kernel_launch(void* const* d_in, const int* in_sizes, int n_in,
                              void* d_out, int out_size) {
    const float* x    = (const float*)d_in[0];
    const float* W    = (const float*)d_in[1];
    const float* Dv   = (const float*)d_in[2];
    const float* bias = (const float*)d_in[3];
    float* out        = (float*)d_out;

    void *pA, *pB, *pF, *pOp, *pB3;
    cudaGetSymbolAddress(&pA,  g_bufA);
    cudaGetSymbolAddress(&pB,  g_bufB);
    cudaGetSymbolAddress(&pF,  g_Fj);
    cudaGetSymbolAddress(&pOp, g_Op);
    cudaGetSymbolAddress(&pB3, g_B3);

    typedef CUresult (*EncodeFn)(CUtensorMap*, CUtensorMapDataType, cuuint32_t, void*,
                                 const cuuint64_t*, const cuuint64_t*, const cuuint32_t*,
                                 const cuuint32_t*, CUtensorMapInterleave, CUtensorMapSwizzle,
                                 CUtensorMapL2promotion, CUtensorMapFloatOOBfill);
    void* fn = nullptr;
    cudaDriverEntryPointQueryResult qr;
    cudaGetDriverEntryPoint("cuTensorMapEncodeTiled", &fn, cudaEnableDefault, &qr);
    EncodeFn encode = (EncodeFn)fn;
    if (!encode) { fprintf(stderr, "no cuTensorMapEncodeTiled\n"); return; }

    auto enc2d = [&](CUtensorMap* tm, void* ptr, uint64_t cols, uint64_t rows,
                     uint32_t bx, uint32_t by) {
        cuuint64_t dims[2]    = {cols, rows};
        cuuint64_t strides[1] = {cols * sizeof(float)};
        cuuint32_t box[2]     = {bx, by};
        cuuint32_t es[2]      = {1, 1};
        encode(tm, CU_TENSOR_MAP_DATA_TYPE_FLOAT32, 2, ptr, dims, strides, box, es,
               CU_TENSOR_MAP_INTERLEAVE_NONE, CU_TENSOR_MAP_SWIZZLE_128B,
               CU_TENSOR_MAP_L2_PROMOTION_L2_128B, CU_TENSOR_MAP_FLOAT_OOB_FILL_NONE);
    };

    CUtensorMap tm_x, tm_f, tm_z, tm_b3, tm_xg, tm_op;
    enc2d(&tm_x,  (void*)x, 4096, 4096,   32, 128);   // G1 A (x)
    enc2d(&tm_f,  pF,       128,  4096,   32, 128);   // G1 B (Fj)
    enc2d(&tm_xg, pA,       64,   262144, 32, 256);   // G2 A (Xg in bufA)
    enc2d(&tm_op, pOp,      64,   4096,   32, 64);    // G2 B
    enc2d(&tm_z,  pB,       128,  131072, 32, 128);   // G3 A (Z in bufB)
    enc2d(&tm_b3, pB3,      128,  128,    32, 128);   // G3 B

    cudaFuncSetAttribute(bc_gemm_tf32, cudaFuncAttributeMaxDynamicSharedMemorySize, SMEM_G);
    cudaFuncSetAttribute(bc_g2,        cudaFuncAttributeMaxDynamicSharedMemorySize, G2_SMEM);

    // prep (merged)
    bc_prep<<<2368, 256>>>(W, Dv);
    // G1: x -> Xg (bufA), transpose fused into scattered epilogue
    bc_gemm_tf32<<<dim3(32, 32), 288, SMEM_G>>>(tm_x, tm_f, (float*)pA, nullptr);
    // G2: Xg (bufA) -> Z (bufB), transpose fused into scattered epilogue
    bc_g2<<<dim3(16, 64), 256, G2_SMEM>>>(tm_xg, tm_op, (float*)pB);
    // G3: Z (bufB) -> out (+bias)
    bc_gemm_tf32<<<dim3(1024, 1), 288, SMEM_G>>>(tm_z, tm_b3, out, bias);
}